// round 1
// baseline (speedup 1.0000x reference)
#include <cuda_runtime.h>

#define NA_ 8192
#define NN_ 65536
#define NE_ 262144
#define DD_ 128
#define NBLK_ 2
#define GEPS_ 1e-5f

// ---- device scratch (static allocations are permitted) ----
__device__ float g_A[NA_ * DD_];    // actor state (updated per block)
__device__ float g_qn[NA_ * DD_];   // relu(GN(actors @ Wq^T))
__device__ float g_agt[NA_ * DD_];  // actors @ Wa^T  (+ edge scatter adds)

// ============================================================================
// Tile GEMM: 32 rows x 128 cols, K in {128, 384}.
// 256 threads. warp w owns rows 4w..4w+3; lane owns cols lane+32*{0,1,2,3}.
// X in smem (row stride XST), W streamed from global in 32-wide K chunks
// through smem with pad-33 layout (conflict-free reads).
// ============================================================================
template <int K, int XST>
__device__ __forceinline__ void gemm_tile(const float* __restrict__ W,
                                          const float* __restrict__ Xs,
                                          float* Ws, float (&acc)[4][4]) {
    const int tid = threadIdx.x;
    const int lane = tid & 31;
    const int warp = tid >> 5;
    const int e0 = warp * 4;
#pragma unroll
    for (int e = 0; e < 4; e++)
#pragma unroll
        for (int jj = 0; jj < 4; jj++) acc[e][jj] = 0.f;

    for (int k0 = 0; k0 < K; k0 += 32) {
        __syncthreads();  // prior chunk compute done / X writes visible
#pragma unroll 4
        for (int idx = tid; idx < 128 * 32; idx += 256) {
            int j = idx >> 5, kk = idx & 31;
            Ws[j * 33 + kk] = W[j * K + k0 + kk];  // coalesced over kk
        }
        __syncthreads();
#pragma unroll
        for (int kk = 0; kk < 32; kk++) {
            float w0 = Ws[(lane      ) * 33 + kk];
            float w1 = Ws[(lane + 32 ) * 33 + kk];
            float w2 = Ws[(lane + 64 ) * 33 + kk];
            float w3 = Ws[(lane + 96 ) * 33 + kk];
#pragma unroll
            for (int e = 0; e < 4; e++) {
                float x = Xs[(e0 + e) * XST + k0 + kk];  // warp broadcast
                acc[e][0] = fmaf(x, w0, acc[e][0]);
                acc[e][1] = fmaf(x, w1, acc[e][1]);
                acc[e][2] = fmaf(x, w2, acc[e][2]);
                acc[e][3] = fmaf(x, w3, acc[e][3]);
            }
        }
    }
    __syncthreads();  // safe to reuse Xs/Ws after return
}

// GroupNorm(1 group over 128 ch) + optional relu, on the warp's 4x4 tile.
__device__ __forceinline__ void gn_act(float (&acc)[4][4],
                                       const float* __restrict__ g,
                                       const float* __restrict__ b,
                                       int lane, bool do_relu) {
    float gv[4], bv[4];
#pragma unroll
    for (int jj = 0; jj < 4; jj++) {
        gv[jj] = g[lane + 32 * jj];
        bv[jj] = b[lane + 32 * jj];
    }
#pragma unroll
    for (int e = 0; e < 4; e++) {
        float s  = acc[e][0] + acc[e][1] + acc[e][2] + acc[e][3];
        float ss = acc[e][0] * acc[e][0] + acc[e][1] * acc[e][1] +
                   acc[e][2] * acc[e][2] + acc[e][3] * acc[e][3];
#pragma unroll
        for (int o = 16; o > 0; o >>= 1) {
            s  += __shfl_xor_sync(0xffffffffu, s, o);
            ss += __shfl_xor_sync(0xffffffffu, ss, o);
        }
        float mu  = s * (1.f / 128.f);
        float var = ss * (1.f / 128.f) - mu * mu;
        float inv = rsqrtf(var + GEPS_);
#pragma unroll
        for (int jj = 0; jj < 4; jj++) {
            float v = (acc[e][jj] - mu) * inv * gv[jj] + bv[jj];
            acc[e][jj] = do_relu ? fmaxf(v, 0.f) : v;
        }
    }
}

// ============================================================================
// Actor pre-pass: qn = relu(GN(A @ Wq^T)); agt = A @ Wa^T
// ============================================================================
__global__ void __launch_bounds__(256)
k_actor_pre(const float* __restrict__ Wq, const float* __restrict__ gq,
            const float* __restrict__ bq, const float* __restrict__ Wa) {
    extern __shared__ float sm[];
    float* Xs = sm;              // 32*128
    float* Ws = sm + 32 * 128;   // 128*33
    const int r0 = blockIdx.x * 32;
    const int tid = threadIdx.x, lane = tid & 31, warp = tid >> 5;
    const int eb = warp * 4;

    for (int idx = tid; idx < 32 * 128; idx += 256)
        Xs[idx] = g_A[r0 * 128 + idx];

    float acc[4][4];
    gemm_tile<128, 128>(Wq, Xs, Ws, acc);
    gn_act(acc, gq, bq, lane, true);
#pragma unroll
    for (int e = 0; e < 4; e++)
#pragma unroll
        for (int jj = 0; jj < 4; jj++)
            g_qn[(r0 + eb + e) * 128 + lane + 32 * jj] = acc[e][jj];

    gemm_tile<128, 128>(Wa, Xs, Ws, acc);
#pragma unroll
    for (int e = 0; e < 4; e++)
#pragma unroll
        for (int jj = 0; jj < 4; jj++)
            g_agt[(r0 + eb + e) * 128 + lane + 32 * jj] = acc[e][jj];
}

// ============================================================================
// Fused edge pipeline (per 32-edge tile):
//   h  = relu(dist0 @ ctr_diff + b0)                  -> Xs seg0
//   d  = relu(GN(dist1 @ h))                          -> Xs seg0 (overwrite)
//   X  = [d | qn[hi] | nodes[wi]]                     (seg1/seg2 prefilled)
//   m  = relu(GN(ctx0 @ X))                           -> Xs seg0 (overwrite)
//   m2 = ctx1 @ m;  atomicAdd(g_agt[hi], m2)
// ============================================================================
__global__ void __launch_bounds__(256)
k_edge(const float* __restrict__ nodes,
       const float* __restrict__ actor_ctrs, const float* __restrict__ node_ctrs,
       const int* __restrict__ hi, const int* __restrict__ wi,
       const float* __restrict__ W0, const float* __restrict__ b0,
       const float* __restrict__ W1, const float* __restrict__ g1,
       const float* __restrict__ b1,
       const float* __restrict__ Wc0, const float* __restrict__ gc0,
       const float* __restrict__ bc0, const float* __restrict__ Wc1) {
    extern __shared__ float sm[];
    float* Xs = sm;              // 32*384 (stride 384)
    float* Ws = sm + 32 * 384;   // 128*33
    const int e0 = blockIdx.x * 32;
    const int tid = threadIdx.x, lane = tid & 31, warp = tid >> 5;
    const int eb = warp * 4;

    // seg0: h = relu(dist0-MLP on ctr diff);  seg1: qn gather;  seg2: node gather
    for (int idx = tid; idx < 32 * 128; idx += 256) {
        int e = idx >> 7, k = idx & 127;
        int h = hi[e0 + e], w = wi[e0 + e];
        float dx = actor_ctrs[h * 2 + 0] - node_ctrs[w * 2 + 0];
        float dy = actor_ctrs[h * 2 + 1] - node_ctrs[w * 2 + 1];
        float v = fmaf(W0[k * 2 + 0], dx, fmaf(W0[k * 2 + 1], dy, b0[k]));
        Xs[e * 384 + k] = fmaxf(v, 0.f);
        Xs[e * 384 + 128 + k] = g_qn[h * 128 + k];
        Xs[e * 384 + 256 + k] = nodes[w * 128 + k];
    }

    float acc[4][4];
    // dist1 (reads seg0 only), GN, relu -> overwrite seg0 with d
    gemm_tile<128, 384>(W1, Xs, Ws, acc);
    gn_act(acc, g1, b1, lane, true);
#pragma unroll
    for (int e = 0; e < 4; e++)
#pragma unroll
        for (int jj = 0; jj < 4; jj++)
            Xs[(eb + e) * 384 + lane + 32 * jj] = acc[e][jj];

    // ctx0 over full 384, GN, relu -> overwrite seg0 with m
    gemm_tile<384, 384>(Wc0, Xs, Ws, acc);
    gn_act(acc, gc0, bc0, lane, true);
#pragma unroll
    for (int e = 0; e < 4; e++)
#pragma unroll
        for (int jj = 0; jj < 4; jj++)
            Xs[(eb + e) * 384 + lane + 32 * jj] = acc[e][jj];

    // ctx1 (reads seg0), scatter-add into agt
    gemm_tile<128, 384>(Wc1, Xs, Ws, acc);
#pragma unroll
    for (int e = 0; e < 4; e++) {
        int h = hi[e0 + eb + e];
#pragma unroll
        for (int jj = 0; jj < 4; jj++)
            atomicAdd(&g_agt[h * 128 + lane + 32 * jj], acc[e][jj]);
    }
}

// ============================================================================
// Actor post-pass: a = relu(GN(agt)); A = relu(GN(a @ Wl^T) + A)
// ============================================================================
__global__ void __launch_bounds__(256)
k_actor_post(const float* __restrict__ ng, const float* __restrict__ nb,
             const float* __restrict__ Wl, const float* __restrict__ lg,
             const float* __restrict__ lb) {
    extern __shared__ float sm[];
    float* Xs = sm;
    float* Ws = sm + 32 * 128;
    const int r0 = blockIdx.x * 32;
    const int tid = threadIdx.x, lane = tid & 31, warp = tid >> 5;
    const int eb = warp * 4;

    float acc[4][4];
#pragma unroll
    for (int e = 0; e < 4; e++)
#pragma unroll
        for (int jj = 0; jj < 4; jj++)
            acc[e][jj] = g_agt[(r0 + eb + e) * 128 + lane + 32 * jj];
    gn_act(acc, ng, nb, lane, true);
#pragma unroll
    for (int e = 0; e < 4; e++)
#pragma unroll
        for (int jj = 0; jj < 4; jj++)
            Xs[(eb + e) * 128 + lane + 32 * jj] = acc[e][jj];

    gemm_tile<128, 128>(Wl, Xs, Ws, acc);
    gn_act(acc, lg, lb, lane, false);
#pragma unroll
    for (int e = 0; e < 4; e++)
#pragma unroll
        for (int jj = 0; jj < 4; jj++) {
            int r = r0 + eb + e, c = lane + 32 * jj;
            float v = acc[e][jj] + g_A[r * 128 + c];
            g_A[r * 128 + c] = fmaxf(v, 0.f);
        }
}

__global__ void k_copy_in(const float* __restrict__ src) {
    int i = blockIdx.x * 256 + threadIdx.x;
    g_A[i] = src[i];
}
__global__ void k_copy_out(float* __restrict__ dst) {
    int i = blockIdx.x * 256 + threadIdx.x;
    dst[i] = g_A[i];
}

extern "C" void kernel_launch(void* const* d_in, const int* in_sizes, int n_in,
                              void* d_out, int out_size) {
    const float* actors     = (const float*)d_in[0];
    const float* nodes      = (const float*)d_in[1];
    const float* actor_ctrs = (const float*)d_in[2];
    const float* node_ctrs  = (const float*)d_in[3];
    const int*   hi         = (const int*)d_in[4];
    const int*   wi         = (const int*)d_in[5];
    const float* dist0_W = (const float*)d_in[6];
    const float* dist0_b = (const float*)d_in[7];
    const float* dist1_W = (const float*)d_in[8];
    const float* dist1_g = (const float*)d_in[9];
    const float* dist1_b = (const float*)d_in[10];
    const float* query_W = (const float*)d_in[11];
    const float* query_g = (const float*)d_in[12];
    const float* query_b = (const float*)d_in[13];
    const float* ctx0_W  = (const float*)d_in[14];
    const float* ctx0_g  = (const float*)d_in[15];
    const float* ctx0_b  = (const float*)d_in[16];
    const float* ctx1_W  = (const float*)d_in[17];
    const float* agt_W   = (const float*)d_in[18];
    const float* norm_g  = (const float*)d_in[19];
    const float* norm_b  = (const float*)d_in[20];
    const float* lin_W   = (const float*)d_in[21];
    const float* lin_g   = (const float*)d_in[22];
    const float* lin_b   = (const float*)d_in[23];

    const int smA = (32 * 128 + 128 * 33) * 4;  // 33280 B
    const int smE = (32 * 384 + 128 * 33) * 4;  // 66048 B
    cudaFuncSetAttribute(k_edge, cudaFuncAttributeMaxDynamicSharedMemorySize, smE);

    k_copy_in<<<NA_ * DD_ / 256, 256>>>(actors);
    for (int i = 0; i < NBLK_; i++) {
        k_actor_pre<<<NA_ / 32, 256, smA>>>(query_W + i * DD_ * DD_,
                                            query_g + i * DD_, query_b + i * DD_,
                                            agt_W + i * DD_ * DD_);
        k_edge<<<NE_ / 32, 256, smE>>>(nodes, actor_ctrs, node_ctrs, hi, wi,
                                       dist0_W + i * DD_ * 2, dist0_b + i * DD_,
                                       dist1_W + i * DD_ * DD_, dist1_g + i * DD_,
                                       dist1_b + i * DD_,
                                       ctx0_W + i * DD_ * 3 * DD_,
                                       ctx0_g + i * DD_, ctx0_b + i * DD_,
                                       ctx1_W + i * DD_ * DD_);
        k_actor_post<<<NA_ / 32, 256, smA>>>(norm_g + i * DD_, norm_b + i * DD_,
                                             lin_W + i * DD_ * DD_,
                                             lin_g + i * DD_, lin_b + i * DD_);
    }
    k_copy_out<<<NA_ * DD_ / 256, 256>>>((float*)d_out);
}

// round 6
// speedup vs baseline: 1.3468x; 1.3468x over previous
#include <cuda_runtime.h>

#define NA_ 8192
#define NN_ 65536
#define NE_ 262144
#define DD_ 128
#define NBLK_ 2
#define GEPS_ 1e-5f

#define ECTA_ 128          // edges (rows) per CTA
#define XST_  130          // Xst row stride in floats ([k][e] layout, 2-way-pad)
#define WPAD_ 33           // Ws row stride

using ull = unsigned long long;

// ---- device scratch ----
__device__ float g_A[NA_ * DD_];    // actor state
__device__ float g_qn[NA_ * DD_];   // relu(GN(actors @ Wq^T))
__device__ float g_agt[NA_ * DD_];  // actors @ Wa^T (+ scatter adds)

// ---- packed f32x2 helpers ----
__device__ __forceinline__ ull ffma2_(ull a, ull b, ull c) {
    ull d;
    asm("fma.rn.f32x2 %0, %1, %2, %3;" : "=l"(d) : "l"(a), "l"(b), "l"(c));
    return d;
}
__device__ __forceinline__ ull pack2_(float x, float y) {
    ull d;
    asm("mov.b64 %0, {%1, %2};" : "=l"(d) : "f"(x), "f"(y));
    return d;
}
__device__ __forceinline__ float2 unpack2_(ull v) {
    float2 f;
    asm("mov.b64 {%0, %1}, %2;" : "=f"(f.x), "=f"(f.y) : "l"(v));
    return f;
}

// ============================================================================
// Packed GEMM pass: out[e][j] (+)= sum_{k<128} X[e][k] * W[j][k0..]
// 256 threads. warp owns 16 edges as 8 packed pairs; lane owns cols lane+32c.
// Xst: smem [k][e] stride XST_ (pairs via LDS.64 broadcast).
// W streamed global->smem in 32-wide K chunks (pad-33, conflict-free reads).
// No trailing sync: callers sync before touching Xst.
// ============================================================================
__device__ __forceinline__ void gemm_p(const float* __restrict__ W, int ldw,
                                       bool init,
                                       const float* __restrict__ Xst,
                                       float* __restrict__ Ws,
                                       ull (&a2)[8][4]) {
    const int tid = threadIdx.x, lane = tid & 31, warp = tid >> 5;
    const int eb = warp * 16;
    if (init) {
#pragma unroll
        for (int p = 0; p < 8; p++)
#pragma unroll
            for (int c = 0; c < 4; c++) a2[p][c] = 0ull;
    }
    for (int k0 = 0; k0 < 128; k0 += 32) {
        __syncthreads();  // prior chunk compute done before Ws overwrite
#pragma unroll
        for (int t = 0; t < 16; t++) {
            int idx = tid + t * 256;
            int j = idx >> 5, kk = idx & 31;
            Ws[j * WPAD_ + kk] = W[j * ldw + k0 + kk];  // coalesced over kk
        }
        __syncthreads();
#pragma unroll
        for (int kk = 0; kk < 32; kk++) {
            const float* xr = &Xst[(k0 + kk) * XST_ + eb];
            ull xp[8];
#pragma unroll
            for (int p = 0; p < 8; p++)
                xp[p] = *(const ull*)(xr + 2 * p);  // LDS.64 broadcast
#pragma unroll
            for (int c = 0; c < 4; c++) {
                float w = Ws[(lane + 32 * c) * WPAD_ + kk];
                ull ww = pack2_(w, w);
#pragma unroll
                for (int p = 0; p < 8; p++)
                    a2[p][c] = ffma2_(xp[p], ww, a2[p][c]);
            }
        }
    }
}

// GroupNorm(1 group / 128 ch) + optional relu on packed tile (in place).
__device__ __forceinline__ void gn_pack(ull (&a2)[8][4],
                                        const float* __restrict__ g,
                                        const float* __restrict__ b,
                                        int lane, bool do_relu) {
    float gv[4], bv[4];
#pragma unroll
    for (int c = 0; c < 4; c++) {
        gv[c] = g[lane + 32 * c];
        bv[c] = b[lane + 32 * c];
    }
#pragma unroll
    for (int p = 0; p < 8; p++) {
        float2 v[4];
#pragma unroll
        for (int c = 0; c < 4; c++) v[c] = unpack2_(a2[p][c]);
        float sl = 0.f, ssl = 0.f, sh = 0.f, ssh = 0.f;
#pragma unroll
        for (int c = 0; c < 4; c++) {
            sl += v[c].x; ssl += v[c].x * v[c].x;
            sh += v[c].y; ssh += v[c].y * v[c].y;
        }
#pragma unroll
        for (int o = 16; o > 0; o >>= 1) {
            sl  += __shfl_xor_sync(0xffffffffu, sl, o);
            ssl += __shfl_xor_sync(0xffffffffu, ssl, o);
            sh  += __shfl_xor_sync(0xffffffffu, sh, o);
            ssh += __shfl_xor_sync(0xffffffffu, ssh, o);
        }
        float mul = sl * (1.f / 128.f);
        float muh = sh * (1.f / 128.f);
        float il = rsqrtf(ssl * (1.f / 128.f) - mul * mul + GEPS_);
        float ih = rsqrtf(ssh * (1.f / 128.f) - muh * muh + GEPS_);
#pragma unroll
        for (int c = 0; c < 4; c++) {
            float x = (v[c].x - mul) * il * gv[c] + bv[c];
            float y = (v[c].y - muh) * ih * gv[c] + bv[c];
            if (do_relu) { x = fmaxf(x, 0.f); y = fmaxf(y, 0.f); }
            a2[p][c] = pack2_(x, y);
        }
    }
}

// Write packed tile back to Xst transposed ([col][edge]); pair -> STS.64.
__device__ __forceinline__ void store_xt(const ull (&a2)[8][4],
                                         float* __restrict__ Xst,
                                         int lane, int eb) {
#pragma unroll
    for (int p = 0; p < 8; p++)
#pragma unroll
        for (int c = 0; c < 4; c++)
            *(ull*)&Xst[(lane + 32 * c) * XST_ + eb + 2 * p] = a2[p][c];
}

// ============================================================================
// Fused edge pipeline, 128 edges per CTA.
// ============================================================================
__global__ void __launch_bounds__(256, 2)
k_edge(const float* __restrict__ nodes,
       const float* __restrict__ actor_ctrs, const float* __restrict__ node_ctrs,
       const int* __restrict__ hi, const int* __restrict__ wi,
       const float* __restrict__ W0, const float* __restrict__ b0,
       const float* __restrict__ W1, const float* __restrict__ g1,
       const float* __restrict__ b1,
       const float* __restrict__ Wc0, const float* __restrict__ gc0,
       const float* __restrict__ bc0, const float* __restrict__ Wc1) {
    extern __shared__ float sm[];
    float* Xst = sm;                    // [128][XST_]
    float* Ws  = sm + 128 * XST_;       // [128][WPAD_]
    __shared__ int   his[ECTA_], wis[ECTA_];
    __shared__ float dxs[ECTA_], dys[ECTA_];

    const int e0 = blockIdx.x * ECTA_;
    const int tid = threadIdx.x, lane = tid & 31, warp = tid >> 5;
    const int eb = warp * 16;

    // prologue: edge indices + ctr diffs (all 256 threads, 128 entries)
    if (tid < ECTA_) {
        int h = hi[e0 + tid], w = wi[e0 + tid];
        his[tid] = h; wis[tid] = w;
    } else {
        int t = tid - ECTA_;
        // second half pre-reads nothing; diffs done below after indices land
        (void)t;
    }
    __syncthreads();
    if (tid < ECTA_) {
        int h = his[tid], w = wis[tid];
        dxs[tid] = actor_ctrs[h * 2 + 0] - node_ctrs[w * 2 + 0];
        dys[tid] = actor_ctrs[h * 2 + 1] - node_ctrs[w * 2 + 1];
    }
    __syncthreads();

    // seg fill: h = relu(dist0 @ diff + b0)  ->  Xst[k][e]
    for (int idx = tid; idx < ECTA_ * 128; idx += 256) {
        int e = idx >> 7, k = idx & 127;
        float v = fmaf(W0[k * 2 + 0], dxs[e], fmaf(W0[k * 2 + 1], dys[e], b0[k]));
        Xst[k * XST_ + e] = fmaxf(v, 0.f);
    }

    ull a2[8][4];
    // d = relu(GN(dist1 @ h))
    gemm_p(W1, 128, true, Xst, Ws, a2);
    gn_pack(a2, g1, b1, lane, true);
    __syncthreads();
    store_xt(a2, Xst, lane, eb);

    // ctx0 over [d | qn[hi] | nodes[wi]] in 3 K=128 passes
    gemm_p(Wc0, 384, true, Xst, Ws, a2);          // pass A: d (already in Xst)
    __syncthreads();
    for (int idx = tid; idx < ECTA_ * 128; idx += 256) {
        int e = idx >> 7, k = idx & 127;
        Xst[k * XST_ + e] = g_qn[his[e] * 128 + k];
    }
    gemm_p(Wc0 + 128, 384, false, Xst, Ws, a2);   // pass B: qn
    __syncthreads();
    for (int idx = tid; idx < ECTA_ * 128; idx += 256) {
        int e = idx >> 7, k = idx & 127;
        Xst[k * XST_ + e] = nodes[wis[e] * 128 + k];
    }
    gemm_p(Wc0 + 256, 384, false, Xst, Ws, a2);   // pass C: nodes
    gn_pack(a2, gc0, bc0, lane, true);
    __syncthreads();
    store_xt(a2, Xst, lane, eb);                  // m

    // m2 = ctx1 @ m, scatter-add
    gemm_p(Wc1, 128, true, Xst, Ws, a2);
#pragma unroll
    for (int p = 0; p < 8; p++) {
        int h0 = his[eb + 2 * p] * 128, h1 = his[eb + 2 * p + 1] * 128;
#pragma unroll
        for (int c = 0; c < 4; c++) {
            float2 v = unpack2_(a2[p][c]);
            atomicAdd(&g_agt[h0 + lane + 32 * c], v.x);
            atomicAdd(&g_agt[h1 + lane + 32 * c], v.y);
        }
    }
}

// ============================================================================
// Actor pre-pass: qn = relu(GN(A @ Wq^T)); agt = A @ Wa^T   (128 rows/CTA)
// ============================================================================
__global__ void __launch_bounds__(256, 2)
k_actor_pre(const float* __restrict__ Wq, const float* __restrict__ gq,
            const float* __restrict__ bq, const float* __restrict__ Wa) {
    extern __shared__ float sm[];
    float* Xst = sm;
    float* Ws  = sm + 128 * XST_;
    const int r0 = blockIdx.x * ECTA_;
    const int tid = threadIdx.x, lane = tid & 31, warp = tid >> 5;
    const int eb = warp * 16;

    for (int idx = tid; idx < ECTA_ * 128; idx += 256) {
        int e = idx >> 7, k = idx & 127;
        Xst[k * XST_ + e] = g_A[(r0 + e) * 128 + k];
    }

    ull a2[8][4];
    gemm_p(Wq, 128, true, Xst, Ws, a2);
    gn_pack(a2, gq, bq, lane, true);
#pragma unroll
    for (int p = 0; p < 8; p++) {
        int r = (r0 + eb + 2 * p) * 128;
#pragma unroll
        for (int c = 0; c < 4; c++) {
            float2 v = unpack2_(a2[p][c]);
            g_qn[r + lane + 32 * c] = v.x;
            g_qn[r + 128 + lane + 32 * c] = v.y;
        }
    }
    gemm_p(Wa, 128, true, Xst, Ws, a2);
#pragma unroll
    for (int p = 0; p < 8; p++) {
        int r = (r0 + eb + 2 * p) * 128;
#pragma unroll
        for (int c = 0; c < 4; c++) {
            float2 v = unpack2_(a2[p][c]);
            g_agt[r + lane + 32 * c] = v.x;
            g_agt[r + 128 + lane + 32 * c] = v.y;
        }
    }
}

// ============================================================================
// Actor post-pass: a = relu(GN(agt)); A = relu(GN(a @ Wl^T) + A)
// ============================================================================
__global__ void __launch_bounds__(256, 2)
k_actor_post(const float* __restrict__ ng, const float* __restrict__ nb,
             const float* __restrict__ Wl, const float* __restrict__ lg,
             const float* __restrict__ lb) {
    extern __shared__ float sm[];
    float* Xst = sm;
    float* Ws  = sm + 128 * XST_;
    const int r0 = blockIdx.x * ECTA_;
    const int tid = threadIdx.x, lane = tid & 31, warp = tid >> 5;
    const int eb = warp * 16;

    ull a2[8][4];
#pragma unroll
    for (int p = 0; p < 8; p++) {
        int r = (r0 + eb + 2 * p) * 128;
#pragma unroll
        for (int c = 0; c < 4; c++)
            a2[p][c] = pack2_(g_agt[r + lane + 32 * c],
                              g_agt[r + 128 + lane + 32 * c]);
    }
    gn_pack(a2, ng, nb, lane, true);
    store_xt(a2, Xst, lane, eb);

    gemm_p(Wl, 128, true, Xst, Ws, a2);
    gn_pack(a2, lg, lb, lane, false);
#pragma unroll
    for (int p = 0; p < 8; p++) {
        int r = (r0 + eb + 2 * p) * 128;
#pragma unroll
        for (int c = 0; c < 4; c++) {
            float2 v = unpack2_(a2[p][c]);
            int i0 = r + lane + 32 * c, i1 = i0 + 128;
            g_A[i0] = fmaxf(v.x + g_A[i0], 0.f);
            g_A[i1] = fmaxf(v.y + g_A[i1], 0.f);
        }
    }
}

__global__ void k_copy_in(const float* __restrict__ src) {
    int i = blockIdx.x * 256 + threadIdx.x;
    g_A[i] = src[i];
}
__global__ void k_copy_out(float* __restrict__ dst) {
    int i = blockIdx.x * 256 + threadIdx.x;
    dst[i] = g_A[i];
}

extern "C" void kernel_launch(void* const* d_in, const int* in_sizes, int n_in,
                              void* d_out, int out_size) {
    const float* actors     = (const float*)d_in[0];
    const float* nodes      = (const float*)d_in[1];
    const float* actor_ctrs = (const float*)d_in[2];
    const float* node_ctrs  = (const float*)d_in[3];
    const int*   hi         = (const int*)d_in[4];
    const int*   wi         = (const int*)d_in[5];
    const float* dist0_W = (const float*)d_in[6];
    const float* dist0_b = (const float*)d_in[7];
    const float* dist1_W = (const float*)d_in[8];
    const float* dist1_g = (const float*)d_in[9];
    const float* dist1_b = (const float*)d_in[10];
    const float* query_W = (const float*)d_in[11];
    const float* query_g = (const float*)d_in[12];
    const float* query_b = (const float*)d_in[13];
    const float* ctx0_W  = (const float*)d_in[14];
    const float* ctx0_g  = (const float*)d_in[15];
    const float* ctx0_b  = (const float*)d_in[16];
    const float* ctx1_W  = (const float*)d_in[17];
    const float* agt_W   = (const float*)d_in[18];
    const float* norm_g  = (const float*)d_in[19];
    const float* norm_b  = (const float*)d_in[20];
    const float* lin_W   = (const float*)d_in[21];
    const float* lin_g   = (const float*)d_in[22];
    const float* lin_b   = (const float*)d_in[23];

    const int smB = (128 * XST_ + 128 * WPAD_) * 4;  // 83,456 B
    cudaFuncSetAttribute(k_edge, cudaFuncAttributeMaxDynamicSharedMemorySize, smB);
    cudaFuncSetAttribute(k_actor_pre, cudaFuncAttributeMaxDynamicSharedMemorySize, smB);
    cudaFuncSetAttribute(k_actor_post, cudaFuncAttributeMaxDynamicSharedMemorySize, smB);

    k_copy_in<<<NA_ * DD_ / 256, 256>>>(actors);
    for (int i = 0; i < NBLK_; i++) {
        k_actor_pre<<<NA_ / ECTA_, 256, smB>>>(query_W + i * DD_ * DD_,
                                               query_g + i * DD_, query_b + i * DD_,
                                               agt_W + i * DD_ * DD_);
        k_edge<<<NE_ / ECTA_, 256, smB>>>(nodes, actor_ctrs, node_ctrs, hi, wi,
                                          dist0_W + i * DD_ * 2, dist0_b + i * DD_,
                                          dist1_W + i * DD_ * DD_, dist1_g + i * DD_,
                                          dist1_b + i * DD_,
                                          ctx0_W + i * DD_ * 3 * DD_,
                                          ctx0_g + i * DD_, ctx0_b + i * DD_,
                                          ctx1_W + i * DD_ * DD_);
        k_actor_post<<<NA_ / ECTA_, 256, smB>>>(norm_g + i * DD_, norm_b + i * DD_,
                                                lin_W + i * DD_ * DD_,
                                                lin_g + i * DD_, lin_b + i * DD_);
    }
    k_copy_out<<<NA_ * DD_ / 256, 256>>>((float*)d_out);
}

// round 11
// speedup vs baseline: 2.0742x; 1.5402x over previous
#include <cuda_runtime.h>
#include <cstdint>

#define NA_ 8192
#define NN_ 65536
#define NE_ 262144
#define DD_ 128
#define NBLK_ 2
#define GEPS_ 1e-5f

#define ECTA_ 128          // rows (edges/actors/nodes) per CTA
#define XST_  130          // Xst row stride in floats ([k][e] layout, 2-way pad)
#define WPAD_ 33           // Ws row stride (conflict-free)

using ull = unsigned long long;

// ---- device scratch ----
__device__ float g_A[NA_ * DD_];      // actor state
__device__ float g_agt[NA_ * DD_];    // actors @ Wa^T (+ scatter adds)
__device__ float g_qctx[NA_ * DD_];   // ctx0_W[:,128:256] @ relu(GN(A @ Wq^T))
__device__ float g_nctx[NN_ * DD_];   // ctx0_W[:,256:384] @ nodes

// ---- packed f32x2 helpers ----
__device__ __forceinline__ ull ffma2_(ull a, ull b, ull c) {
    ull d;
    asm("fma.rn.f32x2 %0, %1, %2, %3;" : "=l"(d) : "l"(a), "l"(b), "l"(c));
    return d;
}
__device__ __forceinline__ ull pack2_(float x, float y) {
    ull d;
    asm("mov.b64 %0, {%1, %2};" : "=l"(d) : "f"(x), "f"(y));
    return d;
}
__device__ __forceinline__ float2 unpack2_(ull v) {
    float2 f;
    asm("mov.b64 {%0, %1}, %2;" : "=f"(f.x), "=f"(f.y) : "l"(v));
    return f;
}
__device__ __forceinline__ uint32_t smem_u32(const void* p) {
    uint32_t a;
    asm("{ .reg .u64 t; cvta.to.shared.u64 t, %1; cvt.u32.u64 %0, t; }"
        : "=r"(a) : "l"(p));
    return a;
}
__device__ __forceinline__ void cp4(uint32_t dst, const float* src) {
    asm volatile("cp.async.ca.shared.global [%0], [%1], 4;"
                 :: "r"(dst), "l"(src) : "memory");
}

// stream one 128x32 W chunk (pad-33 rows) via cp.async; commits one group
__device__ __forceinline__ void load_chunk(uint32_t uWs,
                                           const float* __restrict__ W,
                                           int ldw, int k0) {
    const int tid = threadIdx.x;
#pragma unroll
    for (int t = 0; t < 16; t++) {
        int idx = tid + t * 256;
        int j = idx >> 5, kk = idx & 31;
        cp4(uWs + (uint32_t)(j * WPAD_ + kk) * 4u, W + j * ldw + k0 + kk);
    }
    asm volatile("cp.async.commit_group;" ::: "memory");
}

// ============================================================================
// Double-buffered packed GEMM: out[e][j] (+)= sum_k X[e][k]*W[j][k]
// 256 thr; warp owns 16 rows as 8 packed pairs; lane owns cols lane+32c.
// Xst smem [k][e] (LDS.64 broadcast); W streamed via cp.async (2 buffers).
// Ends with __syncthreads(): Xst/Ws reusable by caller afterward.
// ============================================================================
__device__ __forceinline__ void gemm_db(const float* __restrict__ W, int ldw,
                                        const float* __restrict__ Xst,
                                        const float* __restrict__ Ws0,
                                        const float* __restrict__ Ws1,
                                        uint32_t uWs0, uint32_t uWs1,
                                        ull (&a2)[8][4]) {
    const int tid = threadIdx.x, lane = tid & 31, warp = tid >> 5;
    const int eb = warp * 16;
#pragma unroll
    for (int p = 0; p < 8; p++)
#pragma unroll
        for (int c = 0; c < 4; c++) a2[p][c] = 0ull;

    load_chunk(uWs0, W, ldw, 0);
#pragma unroll 1
    for (int c4 = 0; c4 < 4; c4++) {
        const float* cur = (c4 & 1) ? Ws1 : Ws0;
        if (c4 < 3) {
            load_chunk((c4 & 1) ? uWs0 : uWs1, W, ldw, (c4 + 1) * 32);
            asm volatile("cp.async.wait_group 1;" ::: "memory");
        } else {
            asm volatile("cp.async.wait_group 0;" ::: "memory");
        }
        __syncthreads();   // chunk c4 data visible to all
        const int k0 = c4 * 32;
#pragma unroll
        for (int kk = 0; kk < 32; kk++) {
            const float* xr = &Xst[(k0 + kk) * XST_ + eb];
            ull xp[8];
#pragma unroll
            for (int p = 0; p < 8; p++)
                xp[p] = *(const ull*)(xr + 2 * p);   // LDS.64 broadcast
#pragma unroll
            for (int c = 0; c < 4; c++) {
                float w = cur[(lane + 32 * c) * WPAD_ + kk];
                ull ww = pack2_(w, w);
#pragma unroll
                for (int p = 0; p < 8; p++)
                    a2[p][c] = ffma2_(xp[p], ww, a2[p][c]);
            }
        }
        __syncthreads();   // all reads of cur done before it is refilled
    }
}

// GroupNorm(1 group / 128 ch) + optional relu on packed tile (in place).
__device__ __forceinline__ void gn_pack(ull (&a2)[8][4],
                                        const float* __restrict__ g,
                                        const float* __restrict__ b,
                                        int lane, bool do_relu) {
    float gv[4], bv[4];
#pragma unroll
    for (int c = 0; c < 4; c++) {
        gv[c] = g[lane + 32 * c];
        bv[c] = b[lane + 32 * c];
    }
#pragma unroll
    for (int p = 0; p < 8; p++) {
        float2 v[4];
#pragma unroll
        for (int c = 0; c < 4; c++) v[c] = unpack2_(a2[p][c]);
        float sl = 0.f, ssl = 0.f, sh = 0.f, ssh = 0.f;
#pragma unroll
        for (int c = 0; c < 4; c++) {
            sl += v[c].x; ssl += v[c].x * v[c].x;
            sh += v[c].y; ssh += v[c].y * v[c].y;
        }
#pragma unroll
        for (int o = 16; o > 0; o >>= 1) {
            sl  += __shfl_xor_sync(0xffffffffu, sl, o);
            ssl += __shfl_xor_sync(0xffffffffu, ssl, o);
            sh  += __shfl_xor_sync(0xffffffffu, sh, o);
            ssh += __shfl_xor_sync(0xffffffffu, ssh, o);
        }
        float mul = sl * (1.f / 128.f);
        float muh = sh * (1.f / 128.f);
        float il = rsqrtf(ssl * (1.f / 128.f) - mul * mul + GEPS_);
        float ih = rsqrtf(ssh * (1.f / 128.f) - muh * muh + GEPS_);
#pragma unroll
        for (int c = 0; c < 4; c++) {
            float x = (v[c].x - mul) * il * gv[c] + bv[c];
            float y = (v[c].y - muh) * ih * gv[c] + bv[c];
            if (do_relu) { x = fmaxf(x, 0.f); y = fmaxf(y, 0.f); }
            a2[p][c] = pack2_(x, y);
        }
    }
}

// Write packed tile back to Xst transposed ([col][row-pair] -> STS.64)
__device__ __forceinline__ void store_xt(const ull (&a2)[8][4],
                                         float* __restrict__ Xst,
                                         int lane, int eb) {
#pragma unroll
    for (int p = 0; p < 8; p++)
#pragma unroll
        for (int c = 0; c < 4; c++)
            *(ull*)&Xst[(lane + 32 * c) * XST_ + eb + 2 * p] = a2[p][c];
}

// ============================================================================
// Fused edge pipeline, 128 edges/CTA, 3 GEMM passes.
// ============================================================================
__global__ void __launch_bounds__(256, 2)
k_edge(const float* __restrict__ actor_ctrs, const float* __restrict__ node_ctrs,
       const int* __restrict__ hi, const int* __restrict__ wi,
       const float* __restrict__ W0, const float* __restrict__ b0,
       const float* __restrict__ W1, const float* __restrict__ g1,
       const float* __restrict__ b1,
       const float* __restrict__ Wc0, const float* __restrict__ gc0,
       const float* __restrict__ bc0, const float* __restrict__ Wc1) {
    extern __shared__ float sm[];
    float* Xst = sm;                         // [128][XST_]
    float* Ws0 = sm + 128 * XST_;            // [128][WPAD_]
    float* Ws1 = Ws0 + 128 * WPAD_;
    const uint32_t uWs0 = smem_u32(Ws0), uWs1 = smem_u32(Ws1);
    __shared__ int   his[ECTA_], wis[ECTA_];
    __shared__ float dxs[ECTA_], dys[ECTA_];

    const int e0 = blockIdx.x * ECTA_;
    const int tid = threadIdx.x, lane = tid & 31, warp = tid >> 5;
    const int eb = warp * 16;

    if (tid < ECTA_) {
        int h = hi[e0 + tid], w = wi[e0 + tid];
        his[tid] = h; wis[tid] = w;
        dxs[tid] = actor_ctrs[2 * h] - node_ctrs[2 * w];
        dys[tid] = actor_ctrs[2 * h + 1] - node_ctrs[2 * w + 1];
    }
    __syncthreads();

    // h = relu(dist0 @ diff + b0)  ->  Xst[k][e]
    for (int idx = tid; idx < ECTA_ * 128; idx += 256) {
        int e = idx >> 7, k = idx & 127;
        float v = fmaf(W0[k * 2], dxs[e], fmaf(W0[k * 2 + 1], dys[e], b0[k]));
        Xst[k * XST_ + e] = fmaxf(v, 0.f);
    }
    // Xst writes made visible by gemm_db's internal first sync

    ull a2[8][4];
    // pass 1: d = relu(GN(dist1 @ h))  -> Xst
    gemm_db(W1, 128, Xst, Ws0, Ws1, uWs0, uWs1, a2);
    gn_pack(a2, g1, b1, lane, true);
    store_xt(a2, Xst, lane, eb);

    // pass 2: ctx0-d GEMM; add per-actor/per-node precomputed terms; GN; relu
    gemm_db(Wc0, 384, Xst, Ws0, Ws1, uWs0, uWs1, a2);
#pragma unroll
    for (int p = 0; p < 8; p++) {
        int h0 = his[eb + 2 * p] * 128, h1 = his[eb + 2 * p + 1] * 128;
        int w0 = wis[eb + 2 * p] * 128, w1 = wis[eb + 2 * p + 1] * 128;
#pragma unroll
        for (int c = 0; c < 4; c++) {
            int col = lane + 32 * c;
            float2 v = unpack2_(a2[p][c]);
            v.x += g_qctx[h0 + col] + g_nctx[w0 + col];
            v.y += g_qctx[h1 + col] + g_nctx[w1 + col];
            a2[p][c] = pack2_(v.x, v.y);
        }
    }
    gn_pack(a2, gc0, bc0, lane, true);
    store_xt(a2, Xst, lane, eb);             // m

    // pass 3: m2 = ctx1 @ m; scatter-add
    gemm_db(Wc1, 128, Xst, Ws0, Ws1, uWs0, uWs1, a2);
#pragma unroll
    for (int p = 0; p < 8; p++) {
        int h0 = his[eb + 2 * p] * 128, h1 = his[eb + 2 * p + 1] * 128;
#pragma unroll
        for (int c = 0; c < 4; c++) {
            float2 v = unpack2_(a2[p][c]);
            atomicAdd(&g_agt[h0 + lane + 32 * c], v.x);
            atomicAdd(&g_agt[h1 + lane + 32 * c], v.y);
        }
    }
}

// ============================================================================
// Actor pre-pass: agt = A@Wa^T; qn = relu(GN(A@Wq^T)); qctx = Wc0mid@qn
// ============================================================================
__global__ void __launch_bounds__(256, 2)
k_actor_pre(const float* __restrict__ Wq, const float* __restrict__ gq,
            const float* __restrict__ bq, const float* __restrict__ Wa,
            const float* __restrict__ Wc0mid) {
    extern __shared__ float sm[];
    float* Xst = sm;
    float* Ws0 = sm + 128 * XST_;
    float* Ws1 = Ws0 + 128 * WPAD_;
    const uint32_t uWs0 = smem_u32(Ws0), uWs1 = smem_u32(Ws1);
    const int r0 = blockIdx.x * ECTA_;
    const int tid = threadIdx.x, lane = tid & 31, warp = tid >> 5;
    const int eb = warp * 16;

    for (int idx = tid; idx < ECTA_ * 128; idx += 256) {
        int e = idx >> 7, k = idx & 127;
        Xst[k * XST_ + e] = g_A[(r0 + e) * 128 + k];
    }

    ull a2[8][4];
    // agt = A @ Wa^T
    gemm_db(Wa, 128, Xst, Ws0, Ws1, uWs0, uWs1, a2);
#pragma unroll
    for (int p = 0; p < 8; p++) {
        int r = (r0 + eb + 2 * p) * 128;
#pragma unroll
        for (int c = 0; c < 4; c++) {
            float2 v = unpack2_(a2[p][c]);
            g_agt[r + lane + 32 * c] = v.x;
            g_agt[r + 128 + lane + 32 * c] = v.y;
        }
    }
    // qn = relu(GN(A @ Wq^T))  -> Xst (A no longer needed)
    gemm_db(Wq, 128, Xst, Ws0, Ws1, uWs0, uWs1, a2);
    gn_pack(a2, gq, bq, lane, true);
    store_xt(a2, Xst, lane, eb);
    // qctx = qn @ Wc0mid^T
    gemm_db(Wc0mid, 384, Xst, Ws0, Ws1, uWs0, uWs1, a2);
#pragma unroll
    for (int p = 0; p < 8; p++) {
        int r = (r0 + eb + 2 * p) * 128;
#pragma unroll
        for (int c = 0; c < 4; c++) {
            float2 v = unpack2_(a2[p][c]);
            g_qctx[r + lane + 32 * c] = v.x;
            g_qctx[r + 128 + lane + 32 * c] = v.y;
        }
    }
}

// ============================================================================
// Node pre-pass: nctx = nodes @ Wc0hi^T  (512 CTAs)
// ============================================================================
__global__ void __launch_bounds__(256, 2)
k_nctx(const float* __restrict__ nodes, const float* __restrict__ Wc0hi) {
    extern __shared__ float sm[];
    float* Xst = sm;
    float* Ws0 = sm + 128 * XST_;
    float* Ws1 = Ws0 + 128 * WPAD_;
    const uint32_t uWs0 = smem_u32(Ws0), uWs1 = smem_u32(Ws1);
    const int r0 = blockIdx.x * ECTA_;
    const int tid = threadIdx.x, lane = tid & 31, warp = tid >> 5;
    const int eb = warp * 16;

    for (int idx = tid; idx < ECTA_ * 128; idx += 256) {
        int e = idx >> 7, k = idx & 127;
        Xst[k * XST_ + e] = nodes[(size_t)(r0 + e) * 128 + k];
    }

    ull a2[8][4];
    gemm_db(Wc0hi, 384, Xst, Ws0, Ws1, uWs0, uWs1, a2);
#pragma unroll
    for (int p = 0; p < 8; p++) {
        int r = (r0 + eb + 2 * p) * 128;
#pragma unroll
        for (int c = 0; c < 4; c++) {
            float2 v = unpack2_(a2[p][c]);
            g_nctx[r + lane + 32 * c] = v.x;
            g_nctx[r + 128 + lane + 32 * c] = v.y;
        }
    }
}

// ============================================================================
// Actor post-pass: a = relu(GN(agt)); A = relu(GN(a @ Wl^T) + A)
// ============================================================================
__global__ void __launch_bounds__(256, 2)
k_actor_post(const float* __restrict__ ng, const float* __restrict__ nb,
             const float* __restrict__ Wl, const float* __restrict__ lg,
             const float* __restrict__ lb) {
    extern __shared__ float sm[];
    float* Xst = sm;
    float* Ws0 = sm + 128 * XST_;
    float* Ws1 = Ws0 + 128 * WPAD_;
    const uint32_t uWs0 = smem_u32(Ws0), uWs1 = smem_u32(Ws1);
    const int r0 = blockIdx.x * ECTA_;
    const int tid = threadIdx.x, lane = tid & 31, warp = tid >> 5;
    const int eb = warp * 16;

    ull a2[8][4];
#pragma unroll
    for (int p = 0; p < 8; p++) {
        int r = (r0 + eb + 2 * p) * 128;
#pragma unroll
        for (int c = 0; c < 4; c++)
            a2[p][c] = pack2_(g_agt[r + lane + 32 * c],
                              g_agt[r + 128 + lane + 32 * c]);
    }
    gn_pack(a2, ng, nb, lane, true);
    store_xt(a2, Xst, lane, eb);

    gemm_db(Wl, 128, Xst, Ws0, Ws1, uWs0, uWs1, a2);
    gn_pack(a2, lg, lb, lane, false);
#pragma unroll
    for (int p = 0; p < 8; p++) {
        int r = (r0 + eb + 2 * p) * 128;
#pragma unroll
        for (int c = 0; c < 4; c++) {
            float2 v = unpack2_(a2[p][c]);
            int i0 = r + lane + 32 * c, i1 = i0 + 128;
            g_A[i0] = fmaxf(v.x + g_A[i0], 0.f);
            g_A[i1] = fmaxf(v.y + g_A[i1], 0.f);
        }
    }
}

__global__ void k_copy_in(const float* __restrict__ src) {
    int i = blockIdx.x * 256 + threadIdx.x;
    g_A[i] = src[i];
}
__global__ void k_copy_out(float* __restrict__ dst) {
    int i = blockIdx.x * 256 + threadIdx.x;
    dst[i] = g_A[i];
}

extern "C" void kernel_launch(void* const* d_in, const int* in_sizes, int n_in,
                              void* d_out, int out_size) {
    const float* actors     = (const float*)d_in[0];
    const float* nodes      = (const float*)d_in[1];
    const float* actor_ctrs = (const float*)d_in[2];
    const float* node_ctrs  = (const float*)d_in[3];
    const int*   hi         = (const int*)d_in[4];
    const int*   wi         = (const int*)d_in[5];
    const float* dist0_W = (const float*)d_in[6];
    const float* dist0_b = (const float*)d_in[7];
    const float* dist1_W = (const float*)d_in[8];
    const float* dist1_g = (const float*)d_in[9];
    const float* dist1_b = (const float*)d_in[10];
    const float* query_W = (const float*)d_in[11];
    const float* query_g = (const float*)d_in[12];
    const float* query_b = (const float*)d_in[13];
    const float* ctx0_W  = (const float*)d_in[14];
    const float* ctx0_g  = (const float*)d_in[15];
    const float* ctx0_b  = (const float*)d_in[16];
    const float* ctx1_W  = (const float*)d_in[17];
    const float* agt_W   = (const float*)d_in[18];
    const float* norm_g  = (const float*)d_in[19];
    const float* norm_b  = (const float*)d_in[20];
    const float* lin_W   = (const float*)d_in[21];
    const float* lin_g   = (const float*)d_in[22];
    const float* lin_b   = (const float*)d_in[23];

    const int smB = (128 * XST_ + 2 * 128 * WPAD_) * 4;  // 100,352 B
    cudaFuncSetAttribute(k_edge, cudaFuncAttributeMaxDynamicSharedMemorySize, smB);
    cudaFuncSetAttribute(k_actor_pre, cudaFuncAttributeMaxDynamicSharedMemorySize, smB);
    cudaFuncSetAttribute(k_actor_post, cudaFuncAttributeMaxDynamicSharedMemorySize, smB);
    cudaFuncSetAttribute(k_nctx, cudaFuncAttributeMaxDynamicSharedMemorySize, smB);

    k_copy_in<<<NA_ * DD_ / 256, 256>>>(actors);
    for (int i = 0; i < NBLK_; i++) {
        const float* Wc0 = ctx0_W + i * DD_ * 3 * DD_;
        k_actor_pre<<<NA_ / ECTA_, 256, smB>>>(query_W + i * DD_ * DD_,
                                               query_g + i * DD_, query_b + i * DD_,
                                               agt_W + i * DD_ * DD_,
                                               Wc0 + 128);
        k_nctx<<<NN_ / ECTA_, 256, smB>>>(nodes, Wc0 + 256);
        k_edge<<<NE_ / ECTA_, 256, smB>>>(actor_ctrs, node_ctrs, hi, wi,
                                          dist0_W + i * DD_ * 2, dist0_b + i * DD_,
                                          dist1_W + i * DD_ * DD_, dist1_g + i * DD_,
                                          dist1_b + i * DD_,
                                          Wc0, ctx0_g + i * DD_, ctx0_b + i * DD_,
                                          ctx1_W + i * DD_ * DD_);
        k_actor_post<<<NA_ / ECTA_, 256, smB>>>(norm_g + i * DD_, norm_b + i * DD_,
                                                lin_W + i * DD_ * DD_,
                                                lin_g + i * DD_, lin_b + i * DD_);
    }
    k_copy_out<<<NA_ * DD_ / 256, 256>>>((float*)d_out);
}